// round 2
// baseline (speedup 1.0000x reference)
#include <cuda_runtime.h>
#include <math.h>

// Problem constants
#define CC      50      // MUL
#define HID     64
#define NB      10      // NBASIS
#define NPATHS  5
#define NLAYERS 6
#define BB      64
#define LL      514
#define TT      512     // L-2
#define NT      (BB*TT) // 32768 triplets
#define MAXR    0.06f
#define HALFBAR 0.05f
#define PI_F    3.14159265358979f

// Kernel config
#define WARPS        8
#define NTHREADS     256
#define NBLOCKS      (NT/WARPS)          // 4096
// shared weight buffer: phase A: Wr1(768) + Wr2cols0..99(6400) = 7168
//                       phase B: Ws(2500)+Wg(2500)+Wv(2500)=7500, temps at [7500..12300)
#define WBUF_FLOATS  12300
// per-warp: S(150) V(450) WI(100) HID(64) EMB(12) GEO(5) -> 784 padded
#define PWSZ         784
#define SMEM_FLOATS  (WBUF_FLOATS + WARPS*PWSZ)   // 18572
#define SMEM_BYTES   (SMEM_FLOATS*4)              // 74288

__device__ float g_s1[NLAYERS][CC];          // node-1 scalar state entering layer l
__device__ float g_wbar[NLAYERS][NPATHS*CC]; // intra-edge weights (r=0.05) per layer

__device__ __forceinline__ float siluf(float x){ return x/(1.f+__expf(-x)); }
__device__ __forceinline__ float sigmf(float x){ return 1.f/(1.f+__expf(-x)); }

// ---------------------------------------------------------------------------
// Precompute: per-layer global constants (node-1 s trajectory + intra-edge w)
// ---------------------------------------------------------------------------
__global__ void e3nn_precompute(const float* __restrict__ W_embed,
                                const float* __restrict__ Wr1,
                                const float* __restrict__ br1,
                                const float* __restrict__ Wr2,
                                const float* __restrict__ Ws)
{
    __shared__ float s1[CC], s1n[CC], hid[HID], emb[NB+2];
    __shared__ float fc0s;
    int tid = threadIdx.x;
    if (tid < CC) s1[tid] = W_embed[tid] + W_embed[CC + tid];   // x=[1,1,0] @ W_embed
    if (tid == 0) {
        const float r = HALFBAR;
        float tt = fminf(fmaxf(r/MAXR, 0.f), 1.f);
        float fc = 0.5f*(cosf(PI_F*tt) + 1.f);
        fc0s = fc;
        const float width = MAXR/(float)(NB-1);
        for (int i = 0; i < NB; i++) {
            float ci = MAXR*(float)i/(float)(NB-1);
            float d  = (r - ci)/width;
            emb[i]   = __expf(-d*d)*fc;
        }
        emb[NB]   = 0.f;   // intra edge_attr = one_hot(1) = [0,1]
        emb[NB+1] = 1.f;
    }
    __syncthreads();
    for (int l = 0; l < NLAYERS; l++) {
        if (tid < CC) g_s1[l][tid] = s1[tid];
        if (tid < HID) {
            float acc = br1[l*HID + tid];
            #pragma unroll
            for (int i = 0; i < NB+2; i++) acc += emb[i]*Wr1[(l*(NB+2)+i)*HID + tid];
            hid[tid] = siluf(acc);
        }
        if (tid < CC) {
            float acc = 0.f;
            for (int c = 0; c < CC; c++) acc += s1[c]*Ws[(l*CC + c)*CC + tid];
            s1n[tid] = siluf(acc);
        }
        __syncthreads();
        if (tid < NPATHS*CC) {
            float acc = 0.f;
            for (int j = 0; j < HID; j++) acc += hid[j]*Wr2[(l*HID + j)*(NPATHS*CC) + tid];
            g_wbar[l][tid] = acc*fc0s;
        }
        if (tid < CC) s1[tid] = s1n[tid];
        __syncthreads();
    }
}

// ---------------------------------------------------------------------------
// Main fused kernel: 1 triplet per warp, all 6 layers fused.
// Only nodes 3,4,5 of each triplet are live; node 4 gets its message from the
// globally-constant node 1 via the per-triplet inter edge; nodes 3/5 get
// messages from node 4 via the constant-geometry intra edges (u5 = -u3).
// ---------------------------------------------------------------------------
__global__ void __launch_bounds__(NTHREADS, 2) e3nn_main(
    const float* __restrict__ y,
    const float* __restrict__ W_embed,
    const float* __restrict__ Wr1,
    const float* __restrict__ br1,
    const float* __restrict__ Wr2,
    const float* __restrict__ Ws,
    const float* __restrict__ Wv,
    const float* __restrict__ Wg,
    const float* __restrict__ W_out,
    float* __restrict__ outp)
{
    extern __shared__ float sm[];
    float* wbuf = sm;
    const int tid  = threadIdx.x;
    const int w    = tid >> 5;
    const int lane = tid & 31;

    float* PW   = sm + WBUF_FLOATS + w*PWSZ;
    float* S    = PW;        // [n*50+c], n: 0=node3, 1=node4, 2=node5
    float* V    = PW + 150;  // [(n*50+c)*3 + d]
    float* WI   = PW + 600;  // inter-edge w, paths 0,1: [p*50+c], p<2
    float* HIDs = PW + 700;  // [64]
    float* EMB  = PW + 764;  // [12]
    float* GEO  = PW + 776;  // 0:uIx 1:uIy 2:u3x 3:u3y 4:fcut

    const int g = blockIdx.x*WARPS + w;   // triplet id, always < NT
    const int b = g >> 9;                 // / TT
    const int t = g & 511;                // % TT

    // --- geometry init (lane 0) ---
    if (lane == 0) {
        const float* yb = y + (size_t)(b*LL)*6;
        float c0x = yb[t*6+0],     c0y = yb[t*6+1];
        float c1x = yb[(t+1)*6+0], c1y = yb[(t+1)*6+1];
        float a   = yb[(t+1)*6+2];
        float ex = c0x - c1x, ey = c0y - c1y;      // pos[node1] - pos[node4]
        float r  = sqrtf(ex*ex + ey*ey);
        float inv = 1.f/(r + 1e-12f);
        GEO[0] = ex*inv; GEO[1] = ey*inv;
        GEO[2] = sinf(a); GEO[3] = -cosf(a);       // u3 (node4 -> node3 dir)
        float tt = fminf(fmaxf(r/MAXR, 0.f), 1.f);
        float fc = 0.5f*(cosf(PI_F*tt) + 1.f);
        GEO[4] = fc;
        const float width = MAXR/(float)(NB-1);
        for (int i = 0; i < NB; i++) {
            float ci = MAXR*(float)i/(float)(NB-1);
            float d  = (r - ci)/width;
            EMB[i]   = __expf(-d*d)*fc;
        }
        EMB[NB]   = 1.f;   // inter edge_attr = one_hot(0) = [1,0]
        EMB[NB+1] = 0.f;
    }
    // --- state init ---
    for (int c = lane; c < CC; c += 32) {
        float e0 = W_embed[c], e1 = W_embed[CC+c], e2 = W_embed[2*CC+c];
        S[c]        = e0 + e2;   // node3: attr class 1
        S[50 + c]   = e0 + e1;   // node4: attr class 0
        S[100 + c]  = e0 + e2;   // node5
    }
    for (int i = lane; i < 450; i += 32) V[i] = 0.f;

    const int k1 = lane;
    const int k2 = lane + 32;
    const bool p2 = (k2 < CC);
    const int k2c = p2 ? k2 : 0;

    for (int l = 0; l < NLAYERS; l++) {
        __syncthreads();   // all warps done reading previous phase-B buffers
        // --- Phase A load: Wr1[l] (768) + Wr2[l][:, 0:100] (6400) ---
        {
            const float4* s1p = (const float4*)(Wr1 + (size_t)l*(NB+2)*HID);
            float4* d1 = (float4*)wbuf;
            for (int i = tid; i < 192; i += NTHREADS) d1[i] = s1p[i];
            const float* src2 = Wr2 + (size_t)l*HID*(NPATHS*CC);
            float* dst2 = wbuf + 768;
            for (int idx = tid; idx < HID*100; idx += NTHREADS) {
                int j = idx/100, o = idx - j*100;
                dst2[idx] = src2[j*(NPATHS*CC) + o];
            }
        }
        __syncthreads();
        // --- edge MLP for the inter edge (paths 0,1 only; v_src=0 kills 2..4) ---
        {
            const float* Wr1s = wbuf;
            const float* Wr2s = wbuf + 768;
            for (int j = lane; j < HID; j += 32) {
                float acc = br1[l*HID + j];
                #pragma unroll
                for (int i = 0; i < NB+2; i++) acc += EMB[i]*Wr1s[i*HID + j];
                HIDs[j] = siluf(acc);
            }
            __syncwarp();
            float fc = GEO[4];
            float acc[4] = {0.f, 0.f, 0.f, 0.f};
            for (int j = 0; j < HID; j++) {
                float hj = HIDs[j];
                const float* row = Wr2s + j*100;
                #pragma unroll
                for (int i = 0; i < 4; i++) {
                    int o = lane + 32*i;
                    if (o < 100) acc[i] += hj*row[o];
                }
            }
            #pragma unroll
            for (int i = 0; i < 4; i++) {
                int o = lane + 32*i;
                if (o < 100) WI[o] = acc[i]*fc;
            }
        }
        __syncthreads();   // done with Wr2 smem
        // --- Phase B load: Ws[l], Wg[l], Wv[l] ---
        {
            const float4* sa = (const float4*)(Ws + (size_t)l*CC*CC);
            const float4* sb = (const float4*)(Wg + (size_t)l*CC*CC);
            const float4* sc = (const float4*)(Wv + (size_t)l*CC*CC);
            float4* da = (float4*)wbuf;
            float4* db = (float4*)(wbuf + 2500);
            float4* dc = (float4*)(wbuf + 5000);
            for (int i = tid; i < 625; i += NTHREADS) { da[i]=sa[i]; db[i]=sb[i]; dc[i]=sc[i]; }
        }
        __syncthreads();
        const float* Wss = wbuf;
        const float* Wgs = wbuf + 2500;
        const float* Wvs = wbuf + 5000;
        float* H  = wbuf + 7500 + w*600;   // [n*50+c]
        float* VT = H + 150;               // [(n*50+c)*3+d]
        // --- messages ---
        {
            float uIx = GEO[0], uIy = GEO[1], ux = GEO[2], uy = GEO[3];
            const float* s1l = g_s1[l];
            const float* wb  = g_wbar[l];
            for (int c = lane; c < CC; c += 32) {
                float s1c = s1l[c];
                float s4  = S[50 + c];
                float v4x = V[(50+c)*3+0], v4y = V[(50+c)*3+1], v4z = V[(50+c)*3+2];
                // node4 <- node1 (v1 = 0)
                H[50 + c] = s4 + WI[c]*s1c;
                float w1i = WI[50 + c]*s1c;
                VT[(50+c)*3+0] = v4x + w1i*uIx;
                VT[(50+c)*3+1] = v4y + w1i*uIy;
                VT[(50+c)*3+2] = v4z;
                // node3 / node5 <- node4  (u5 = -u3, Y2 even in u)
                float dotc = v4x*ux + v4y*uy;           // u3z = 0
                float w0 = wb[c], w1 = wb[50+c], w2 = wb[100+c], w3 = wb[150+c], w4 = wb[200+c];
                float base = w0*s4;
                H[c]       = S[c]       + base + w2*dotc;
                H[100 + c] = S[100 + c] + base - w2*dotc;
                float cx = -v4z*uy, cy = v4z*ux, cz = v4x*uy - v4y*ux;   // v4 x u3
                float y2x = dotc*ux - v4x*(1.f/3.f);
                float y2y = dotc*uy - v4y*(1.f/3.f);
                float y2z = -v4z*(1.f/3.f);
                float sx = w1*s4;
                VT[c*3+0] = V[c*3+0] + sx*ux + w3*cx + w4*y2x;
                VT[c*3+1] = V[c*3+1] + sx*uy + w3*cy + w4*y2y;
                VT[c*3+2] = V[c*3+2]         + w3*cz + w4*y2z;
                VT[(100+c)*3+0] = V[(100+c)*3+0] - sx*ux - w3*cx + w4*y2x;
                VT[(100+c)*3+1] = V[(100+c)*3+1] - sx*uy - w3*cy + w4*y2y;
                VT[(100+c)*3+2] = V[(100+c)*3+2]         - w3*cz + w4*y2z;
            }
            __syncwarp();
        }
        // --- node updates: s=silu(h@Ws), gate=sigmoid(h@Wg), v=(vt@Wv)*gate ---
        #pragma unroll
        for (int n = 0; n < 3; n++) {
            float aS1=0,aG1=0,aVx1=0,aVy1=0,aVz1=0;
            float aS2=0,aG2=0,aVx2=0,aVy2=0,aVz2=0;
            const float* Hn = H  + n*50;
            const float* Vn = VT + n*150;
            #pragma unroll 2
            for (int c = 0; c < CC; c++) {
                float hh = Hn[c];
                float vx = Vn[c*3], vy = Vn[c*3+1], vz = Vn[c*3+2];
                int idx = c*50;
                float wsk = Wss[idx+k1], wgk = Wgs[idx+k1], wvk = Wvs[idx+k1];
                aS1 += hh*wsk; aG1 += hh*wgk;
                aVx1 += vx*wvk; aVy1 += vy*wvk; aVz1 += vz*wvk;
                float wsk2 = Wss[idx+k2c], wgk2 = Wgs[idx+k2c], wvk2 = Wvs[idx+k2c];
                aS2 += hh*wsk2; aG2 += hh*wgk2;
                aVx2 += vx*wvk2; aVy2 += vy*wvk2; aVz2 += vz*wvk2;
            }
            float g1 = sigmf(aG1);
            S[n*50 + k1] = siluf(aS1);
            V[(n*50+k1)*3+0] = aVx1*g1;
            V[(n*50+k1)*3+1] = aVy1*g1;
            V[(n*50+k1)*3+2] = aVz1*g1;
            if (p2) {
                float g2 = sigmf(aG2);
                S[n*50 + k2] = siluf(aS2);
                V[(n*50+k2)*3+0] = aVx2*g2;
                V[(n*50+k2)*3+1] = aVy2*g2;
                V[(n*50+k2)*3+2] = aVz2*g2;
            }
        }
        __syncwarp();
    }

    // --- epilogue: out[n] = sum_c v[n][c]*W_out[c]; write result row ---
    float p[9];
    #pragma unroll
    for (int i = 0; i < 9; i++) p[i] = 0.f;
    for (int c = lane; c < CC; c += 32) {
        float wo = W_out[c];
        #pragma unroll
        for (int n = 0; n < 3; n++) {
            p[n*3+0] += wo*V[(n*50+c)*3+0];
            p[n*3+1] += wo*V[(n*50+c)*3+1];
            p[n*3+2] += wo*V[(n*50+c)*3+2];
        }
    }
    #pragma unroll
    for (int off = 16; off > 0; off >>= 1) {
        #pragma unroll
        for (int i = 0; i < 9; i++) p[i] += __shfl_xor_sync(0xffffffffu, p[i], off);
    }
    if (lane == 0) {
        float o3x = p[0], o3y = p[1];
        float o4x = p[3], o4y = p[4];
        float o5x = p[6], o5y = p[7];
        float rx = o3x + o4x + o5x;
        float ry = o3y + o4y + o5y;
        float ux = GEO[2], uy = GEO[3];
        float offx = -HALFBAR*ux, offy = -HALFBAR*uy;   // off vector of middle point
        float rz = (offx*o3y - offy*o3x) - (offx*o5y - offy*o5x);
        float* o = outp + ((size_t)(b*LL) + (t+1))*3;
        o[0] = rx; o[1] = ry; o[2] = rz;
    }
}

// ---------------------------------------------------------------------------
extern "C" void kernel_launch(void* const* d_in, const int* in_sizes, int n_in,
                              void* d_out, int out_size)
{
    const float* y       = (const float*)d_in[0];
    const float* W_embed = (const float*)d_in[1];
    const float* Wr1     = (const float*)d_in[2];
    const float* br1     = (const float*)d_in[3];
    const float* Wr2     = (const float*)d_in[4];
    const float* Ws      = (const float*)d_in[5];
    const float* Wv      = (const float*)d_in[6];
    const float* Wg      = (const float*)d_in[7];
    const float* W_out   = (const float*)d_in[8];
    float* outp = (float*)d_out;

    cudaFuncSetAttribute(e3nn_main, cudaFuncAttributeMaxDynamicSharedMemorySize, SMEM_BYTES);

    // zero whole output (borders t=0, t=L-1 must be 0; interior overwritten)
    cudaMemsetAsync(d_out, 0, (size_t)out_size*sizeof(float), 0);
    e3nn_precompute<<<1, 256>>>(W_embed, Wr1, br1, Wr2, Ws);
    e3nn_main<<<NBLOCKS, NTHREADS, SMEM_BYTES>>>(y, W_embed, Wr1, br1, Wr2,
                                                 Ws, Wv, Wg, W_out, outp);
}

// round 4
// speedup vs baseline: 1.5516x; 1.5516x over previous
#include <cuda_runtime.h>
#include <math.h>

// Problem constants
#define CC      50
#define HID     64
#define NB      10
#define NPATHS  5
#define NLAYERS 6
#define BB      64
#define LL      514
#define TT      512
#define NT      (BB*TT)
#define MAXR    0.06f
#define HALFBAR 0.05f
#define PI_F    3.14159265358979f

// Kernel config: 4 warps/block, 4 triplets per warp
#define TRIPW    4
#define WPB      4
#define NTHREADS 128
#define TPB      (WPB*TRIPW)      // 16 triplets per block
#define NBLOCKS  (NT/TPB)         // 2048

// Shared memory layout (float offsets)
// wbuf phase A: Wr1s [0,768), Wr2s(cols 0..99) [768,7168)
// wbuf phase B: Wss [0,2600) Wgs [2600,5200) Wvs [5200,7800)  (rows 50,51 zeroed)
#define WSS_OFF    0
#define WGS_OFF    2600
#define WVS_OFF    5200
#define WR2_OFF    768
#define OFF_HVT    7800
#define HVT_TRIP   624            // H: 3*52, V: 9*52
#define OFF_EMB    (OFF_HVT + TPB*HVT_TRIP)   // 17784
#define OFF_HIDS   (OFF_EMB + TPB*12)          // 17976
#define SMEM_FLOATS (OFF_HIDS + TPB*64)        // 19000
#define SMEM_BYTES (SMEM_FLOATS*4)             // 76000

__device__ float g_s1[NLAYERS][CC];
__device__ float g_wbar[NLAYERS][NPATHS*CC];

__device__ __forceinline__ float siluf(float x){ return x/(1.f+__expf(-x)); }
__device__ __forceinline__ float sigmf(float x){ return 1.f/(1.f+__expf(-x)); }

// ---------------------------------------------------------------------------
// Precompute per-layer global constants (node-1 s trajectory + intra-edge w)
// ---------------------------------------------------------------------------
__global__ void e3nn_precompute(const float* __restrict__ W_embed,
                                const float* __restrict__ Wr1,
                                const float* __restrict__ br1,
                                const float* __restrict__ Wr2,
                                const float* __restrict__ Ws)
{
    __shared__ float s1[CC], s1n[CC], hid[HID], emb[NB+2];
    __shared__ float fc0s;
    int tid = threadIdx.x;
    if (tid < CC) s1[tid] = W_embed[tid] + W_embed[CC + tid];
    if (tid == 0) {
        const float r = HALFBAR;
        float tt = fminf(fmaxf(r/MAXR, 0.f), 1.f);
        float fc = 0.5f*(cosf(PI_F*tt) + 1.f);
        fc0s = fc;
        const float width = MAXR/(float)(NB-1);
        for (int i = 0; i < NB; i++) {
            float ci = MAXR*(float)i/(float)(NB-1);
            float d  = (r - ci)/width;
            emb[i]   = __expf(-d*d)*fc;
        }
        emb[NB]   = 0.f;
        emb[NB+1] = 1.f;
    }
    __syncthreads();
    for (int l = 0; l < NLAYERS; l++) {
        if (tid < CC) g_s1[l][tid] = s1[tid];
        if (tid < HID) {
            float acc = br1[l*HID + tid];
            #pragma unroll
            for (int i = 0; i < NB+2; i++) acc += emb[i]*Wr1[(l*(NB+2)+i)*HID + tid];
            hid[tid] = siluf(acc);
        }
        if (tid < CC) {
            float acc = 0.f;
            for (int c = 0; c < CC; c++) acc += s1[c]*Ws[(l*CC + c)*CC + tid];
            s1n[tid] = siluf(acc);
        }
        __syncthreads();
        if (tid < NPATHS*CC) {
            float acc = 0.f;
            for (int j = 0; j < HID; j++) acc += hid[j]*Wr2[(l*HID + j)*(NPATHS*CC) + tid];
            g_wbar[l][tid] = acc*fc0s;
        }
        if (tid < CC) s1[tid] = s1n[tid];
        __syncthreads();
    }
}

// ---------------------------------------------------------------------------
// Main fused kernel: 4 triplets per warp, state in registers, all 6 layers.
// ---------------------------------------------------------------------------
__global__ void __launch_bounds__(NTHREADS, 2) e3nn_main(
    const float* __restrict__ y,
    const float* __restrict__ W_embed,
    const float* __restrict__ Wr1,
    const float* __restrict__ br1,
    const float* __restrict__ Wr2,
    const float* __restrict__ Ws,
    const float* __restrict__ Wv,
    const float* __restrict__ Wg,
    const float* __restrict__ W_out,
    float* __restrict__ outp)
{
    extern __shared__ float sm[];
    const int tid  = threadIdx.x;
    const int w    = tid >> 5;
    const int lane = tid & 31;
    const int k    = lane;
    const bool act = (k < 25);
    const int c0   = 2*k;          // valid only if act
    const int c1   = c0 + 1;

    const int gbase = blockIdx.x*TPB + w*TRIPW;

    // ---- geometry init: lanes 0..3 each handle one triplet ----
    float myUIx=0.f, myUIy=0.f, myU3x=0.f, myU3y=0.f, myFc=0.f;
    if (lane < TRIPW) {
        int g = gbase + lane;
        int b = g >> 9;
        int t = g & 511;
        const float* yb = y + ((size_t)b*LL + t)*6;
        float p0x = yb[0],  p0y = yb[1];
        float p1x = yb[6],  p1y = yb[7];
        float a   = yb[8];
        float ex = p0x - p1x, ey = p0y - p1y;       // pos[node1]-pos[node4]
        float r  = sqrtf(ex*ex + ey*ey);
        float inv = 1.f/(r + 1e-12f);
        myUIx = ex*inv; myUIy = ey*inv;
        myU3x = sinf(a); myU3y = -cosf(a);
        float tt = fminf(fmaxf(r/MAXR, 0.f), 1.f);
        myFc = 0.5f*(cosf(PI_F*tt) + 1.f);
        const float width = MAXR/(float)(NB-1);
        float* embp = sm + OFF_EMB + (w*TRIPW + lane)*12;
        for (int i = 0; i < NB; i++) {
            float ci = MAXR*(float)i/(float)(NB-1);
            float d  = (r - ci)/width;
            embp[i]  = __expf(-d*d)*myFc;
        }
        embp[NB]   = 1.f;
        embp[NB+1] = 0.f;
    }
    float uIx[TRIPW], uIy[TRIPW], u3x[TRIPW], u3y[TRIPW], fcT[TRIPW];
    #pragma unroll
    for (int t = 0; t < TRIPW; t++) {
        uIx[t] = __shfl_sync(0xffffffffu, myUIx, t);
        uIy[t] = __shfl_sync(0xffffffffu, myUIy, t);
        u3x[t] = __shfl_sync(0xffffffffu, myU3x, t);
        u3y[t] = __shfl_sync(0xffffffffu, myU3y, t);
        fcT[t] = __shfl_sync(0xffffffffu, myFc,  t);
    }

    // zero H/VT region (so the 50/51 pads are clean forever)
    for (int i = tid; i < TPB*HVT_TRIP; i += NTHREADS) sm[OFF_HVT + i] = 0.f;

    // ---- register state ----
    float s[TRIPW][3][2];
    float v[TRIPW][3][2][3];
    #pragma unroll
    for (int t = 0; t < TRIPW; t++)
        #pragma unroll
        for (int n = 0; n < 3; n++)
            #pragma unroll
            for (int q = 0; q < 2; q++) {
                s[t][n][q] = 0.f;
                v[t][n][q][0] = v[t][n][q][1] = v[t][n][q][2] = 0.f;
            }
    if (act) {
        float e00 = W_embed[c0],      e01 = W_embed[c1];
        float e10 = W_embed[CC+c0],   e11 = W_embed[CC+c1];
        float e20 = W_embed[2*CC+c0], e21 = W_embed[2*CC+c1];
        #pragma unroll
        for (int t = 0; t < TRIPW; t++) {
            s[t][0][0] = e00 + e20;  s[t][0][1] = e01 + e21;   // node3
            s[t][1][0] = e00 + e10;  s[t][1][1] = e01 + e11;   // node4
            s[t][2][0] = e00 + e20;  s[t][2][1] = e01 + e21;   // node5
        }
    }

    for (int l = 0; l < NLAYERS; l++) {
        __syncthreads();   // prior layer done reading wbuf / HVT pads zeroed
        // ---- Phase A staging: Wr1[l] (768) + Wr2[l][:,0:100] (6400) ----
        {
            const float4* s1p = (const float4*)(Wr1 + (size_t)l*(NB+2)*HID);
            float4* d1 = (float4*)sm;
            for (int i = tid; i < 192; i += NTHREADS) d1[i] = s1p[i];
            const float* src2 = Wr2 + (size_t)l*HID*(NPATHS*CC);
            float* dst2 = sm + WR2_OFF;
            for (int idx = tid; idx < HID*100; idx += NTHREADS) {
                int j = idx/100, o = idx - j*100;
                dst2[idx] = src2[j*(NPATHS*CC) + o];
            }
        }
        __syncthreads();
        // ---- hid per triplet (all lanes: j=lane, lane+32) ----
        {
            float a0[TRIPW], a1[TRIPW];
            float b0 = br1[l*HID + lane];
            float b1 = br1[l*HID + lane + 32];
            #pragma unroll
            for (int t = 0; t < TRIPW; t++) { a0[t] = b0; a1[t] = b1; }
            #pragma unroll
            for (int i = 0; i < NB+2; i++) {
                float w0v = sm[i*HID + lane];
                float w1v = sm[i*HID + lane + 32];
                #pragma unroll
                for (int t = 0; t < TRIPW; t++) {
                    float e = sm[OFF_EMB + (w*TRIPW + t)*12 + i];
                    a0[t] += e*w0v;
                    a1[t] += e*w1v;
                }
            }
            #pragma unroll
            for (int t = 0; t < TRIPW; t++) {
                sm[OFF_HIDS + (w*TRIPW+t)*64 + lane]      = siluf(a0[t]);
                sm[OFF_HIDS + (w*TRIPW+t)*64 + lane + 32] = siluf(a1[t]);
            }
        }
        __syncwarp();
        // ---- inter-edge weights: paths 0,1 (v_src=0 kills paths 2..4) ----
        float wi[TRIPW][4];
        #pragma unroll
        for (int t = 0; t < TRIPW; t++)
            wi[t][0]=wi[t][1]=wi[t][2]=wi[t][3]=0.f;
        if (act) {
            #pragma unroll 1
            for (int j4 = 0; j4 < HID; j4 += 4) {
                float4 hv[TRIPW];
                #pragma unroll
                for (int t = 0; t < TRIPW; t++)
                    hv[t] = *(const float4*)&sm[OFF_HIDS + (w*TRIPW+t)*64 + j4];
                #pragma unroll
                for (int jo = 0; jo < 4; jo++) {
                    float2 wa = *(const float2*)&sm[WR2_OFF + (j4+jo)*100 + c0];
                    float2 wc = *(const float2*)&sm[WR2_OFF + (j4+jo)*100 + 50 + c0];
                    #pragma unroll
                    for (int t = 0; t < TRIPW; t++) {
                        float hj = (jo==0)?hv[t].x:(jo==1)?hv[t].y:(jo==2)?hv[t].z:hv[t].w;
                        wi[t][0] += hj*wa.x;
                        wi[t][1] += hj*wa.y;
                        wi[t][2] += hj*wc.x;
                        wi[t][3] += hj*wc.y;
                    }
                }
            }
            #pragma unroll
            for (int t = 0; t < TRIPW; t++) {
                wi[t][0]*=fcT[t]; wi[t][1]*=fcT[t]; wi[t][2]*=fcT[t]; wi[t][3]*=fcT[t];
            }
        }
        // ---- messages -> H/VT smem ----
        if (act) {
            float wb0[2], wb1[2], wb2[2], wb3[2], wb4[2], s1v[2];
            #pragma unroll
            for (int q = 0; q < 2; q++) {
                int cq = c0 + q;
                wb0[q] = g_wbar[l][cq];
                wb1[q] = g_wbar[l][50+cq];
                wb2[q] = g_wbar[l][100+cq];
                wb3[q] = g_wbar[l][150+cq];
                wb4[q] = g_wbar[l][200+cq];
                s1v[q] = g_s1[l][cq];
            }
            #pragma unroll
            for (int t = 0; t < TRIPW; t++) {
                float* hb = sm + OFF_HVT + (w*TRIPW+t)*HVT_TRIP;
                float H3[2], H4[2], H5[2];
                float V3[2][3], V4[2][3], V5[2][3];
                float ux = u3x[t], uy = u3y[t];
                #pragma unroll
                for (int q = 0; q < 2; q++) {
                    float s4  = s[t][1][q];
                    float v4x = v[t][1][q][0], v4y = v[t][1][q][1], v4z = v[t][1][q][2];
                    // node4 <- node1 (v1 = 0)
                    H4[q] = s4 + wi[t][q]*s1v[q];
                    float w1i = wi[t][2+q]*s1v[q];
                    V4[q][0] = v4x + w1i*uIx[t];
                    V4[q][1] = v4y + w1i*uIy[t];
                    V4[q][2] = v4z;
                    // node3 / node5 <- node4 (u5=-u3; Y2 even in u)
                    float dotc = v4x*ux + v4y*uy;
                    float base = wb0[q]*s4;
                    H3[q] = s[t][0][q] + base + wb2[q]*dotc;
                    H5[q] = s[t][2][q] + base - wb2[q]*dotc;
                    float cx = -v4z*uy, cy = v4z*ux, cz = v4x*uy - v4y*ux;
                    float y2x = dotc*ux - v4x*(1.f/3.f);
                    float y2y = dotc*uy - v4y*(1.f/3.f);
                    float y2z = -v4z*(1.f/3.f);
                    float sx = wb1[q]*s4;
                    V3[q][0] = v[t][0][q][0] + sx*ux + wb3[q]*cx + wb4[q]*y2x;
                    V3[q][1] = v[t][0][q][1] + sx*uy + wb3[q]*cy + wb4[q]*y2y;
                    V3[q][2] = v[t][0][q][2]         + wb3[q]*cz + wb4[q]*y2z;
                    V5[q][0] = v[t][2][q][0] - sx*ux - wb3[q]*cx + wb4[q]*y2x;
                    V5[q][1] = v[t][2][q][1] - sx*uy - wb3[q]*cy + wb4[q]*y2y;
                    V5[q][2] = v[t][2][q][2]         - wb3[q]*cz + wb4[q]*y2z;
                }
                *(float2*)&hb[0*52 + c0] = make_float2(H3[0], H3[1]);
                *(float2*)&hb[1*52 + c0] = make_float2(H4[0], H4[1]);
                *(float2*)&hb[2*52 + c0] = make_float2(H5[0], H5[1]);
                #pragma unroll
                for (int d = 0; d < 3; d++) {
                    *(float2*)&hb[156 + (0*3+d)*52 + c0] = make_float2(V3[0][d], V3[1][d]);
                    *(float2*)&hb[156 + (1*3+d)*52 + c0] = make_float2(V4[0][d], V4[1][d]);
                    *(float2*)&hb[156 + (2*3+d)*52 + c0] = make_float2(V5[0][d], V5[1][d]);
                }
            }
        }
        __syncthreads();   // Wr2s done being read; messages written
        // ---- Phase B staging: Ws/Wg/Wv + zero pad rows 50,51 ----
        {
            const float4* sa = (const float4*)(Ws + (size_t)l*CC*CC);
            const float4* sb = (const float4*)(Wg + (size_t)l*CC*CC);
            const float4* sc = (const float4*)(Wv + (size_t)l*CC*CC);
            float4* da = (float4*)(sm + WSS_OFF);
            float4* db = (float4*)(sm + WGS_OFF);
            float4* dc = (float4*)(sm + WVS_OFF);
            for (int i = tid; i < 625; i += NTHREADS) { da[i]=sa[i]; db[i]=sb[i]; dc[i]=sc[i]; }
            for (int i = tid; i < 100; i += NTHREADS) {
                sm[WSS_OFF + 2500 + i] = 0.f;
                sm[WGS_OFF + 2500 + i] = 0.f;
                sm[WVS_OFF + 2500 + i] = 0.f;
            }
        }
        __syncthreads();
        // ---- node update: s=silu(H@Ws), gate=sigm(H@Wg), v=(VT@Wv)*gate ----
        if (act) {
            #pragma unroll 1
            for (int n = 0; n < 3; n++) {
                float aS[TRIPW][2], aG[TRIPW][2], aVx[TRIPW][2], aVy[TRIPW][2], aVz[TRIPW][2];
                #pragma unroll
                for (int t = 0; t < TRIPW; t++) {
                    aS[t][0]=aS[t][1]=aG[t][0]=aG[t][1]=0.f;
                    aVx[t][0]=aVx[t][1]=aVy[t][0]=aVy[t][1]=aVz[t][0]=aVz[t][1]=0.f;
                }
                #pragma unroll 1
                for (int cg = 0; cg < 52; cg += 4) {
                    float2 wsv[4], wgv[4], wvv[4];
                    #pragma unroll
                    for (int i = 0; i < 4; i++) {
                        wsv[i] = *(const float2*)&sm[WSS_OFF + (cg+i)*CC + c0];
                        wgv[i] = *(const float2*)&sm[WGS_OFF + (cg+i)*CC + c0];
                        wvv[i] = *(const float2*)&sm[WVS_OFF + (cg+i)*CC + c0];
                    }
                    #pragma unroll
                    for (int t = 0; t < TRIPW; t++) {
                        const float* hb = sm + OFF_HVT + (w*TRIPW+t)*HVT_TRIP;
                        float4 h4  = *(const float4*)&hb[n*52 + cg];
                        float4 vx4 = *(const float4*)&hb[156 + (n*3+0)*52 + cg];
                        float4 vy4 = *(const float4*)&hb[156 + (n*3+1)*52 + cg];
                        float4 vz4 = *(const float4*)&hb[156 + (n*3+2)*52 + cg];
                        #pragma unroll
                        for (int i = 0; i < 4; i++) {
                            float hc  = (i==0)?h4.x :(i==1)?h4.y :(i==2)?h4.z :h4.w;
                            float vxc = (i==0)?vx4.x:(i==1)?vx4.y:(i==2)?vx4.z:vx4.w;
                            float vyc = (i==0)?vy4.x:(i==1)?vy4.y:(i==2)?vy4.z:vy4.w;
                            float vzc = (i==0)?vz4.x:(i==1)?vz4.y:(i==2)?vz4.z:vz4.w;
                            aS[t][0]  += hc*wsv[i].x;  aS[t][1]  += hc*wsv[i].y;
                            aG[t][0]  += hc*wgv[i].x;  aG[t][1]  += hc*wgv[i].y;
                            aVx[t][0] += vxc*wvv[i].x; aVx[t][1] += vxc*wvv[i].y;
                            aVy[t][0] += vyc*wvv[i].x; aVy[t][1] += vyc*wvv[i].y;
                            aVz[t][0] += vzc*wvv[i].x; aVz[t][1] += vzc*wvv[i].y;
                        }
                    }
                }
                #pragma unroll
                for (int t = 0; t < TRIPW; t++)
                    #pragma unroll
                    for (int q = 0; q < 2; q++) {
                        float gg = sigmf(aG[t][q]);
                        s[t][n][q]    = siluf(aS[t][q]);
                        v[t][n][q][0] = aVx[t][q]*gg;
                        v[t][n][q][1] = aVy[t][q]*gg;
                        v[t][n][q][2] = aVz[t][q]*gg;
                    }
            }
        }
    }

    // ---- epilogue ----
    float p[TRIPW][9];
    #pragma unroll
    for (int t = 0; t < TRIPW; t++)
        #pragma unroll
        for (int i = 0; i < 9; i++) p[t][i] = 0.f;
    if (act) {
        #pragma unroll
        for (int q = 0; q < 2; q++) {
            float wo = W_out[c0+q];
            #pragma unroll
            for (int t = 0; t < TRIPW; t++)
                #pragma unroll
                for (int n = 0; n < 3; n++)
                    #pragma unroll
                    for (int d = 0; d < 3; d++)
                        p[t][n*3+d] += wo*v[t][n][q][d];
        }
    }
    #pragma unroll
    for (int off = 16; off > 0; off >>= 1)
        #pragma unroll
        for (int t = 0; t < TRIPW; t++)
            #pragma unroll
            for (int i = 0; i < 9; i++)
                p[t][i] += __shfl_xor_sync(0xffffffffu, p[t][i], off);
    if (lane == 0) {
        #pragma unroll
        for (int t = 0; t < TRIPW; t++) {
            int g = gbase + t;
            int b = g >> 9;
            int tt = g & 511;
            float rx = p[t][0] + p[t][3] + p[t][6];
            float ry = p[t][1] + p[t][4] + p[t][7];
            float offx = -HALFBAR*u3x[t], offy = -HALFBAR*u3y[t];
            float rz = (offx*p[t][1] - offy*p[t][0]) - (offx*p[t][7] - offy*p[t][6]);
            float* o = outp + ((size_t)b*LL + (tt+1))*3;
            o[0] = rx; o[1] = ry; o[2] = rz;
        }
    }
}

// ---------------------------------------------------------------------------
extern "C" void kernel_launch(void* const* d_in, const int* in_sizes, int n_in,
                              void* d_out, int out_size)
{
    const float* y       = (const float*)d_in[0];
    const float* W_embed = (const float*)d_in[1];
    const float* Wr1     = (const float*)d_in[2];
    const float* br1     = (const float*)d_in[3];
    const float* Wr2     = (const float*)d_in[4];
    const float* Ws      = (const float*)d_in[5];
    const float* Wv      = (const float*)d_in[6];
    const float* Wg      = (const float*)d_in[7];
    const float* W_out   = (const float*)d_in[8];
    float* outp = (float*)d_out;

    cudaFuncSetAttribute(e3nn_main, cudaFuncAttributeMaxDynamicSharedMemorySize, SMEM_BYTES);

    cudaMemsetAsync(d_out, 0, (size_t)out_size*sizeof(float), 0);
    e3nn_precompute<<<1, 256>>>(W_embed, Wr1, br1, Wr2, Ws);
    e3nn_main<<<NBLOCKS, NTHREADS, SMEM_BYTES>>>(y, W_embed, Wr1, br1, Wr2,
                                                 Ws, Wv, Wg, W_out, outp);
}